// round 14
// baseline (speedup 1.0000x reference)
#include <cuda_runtime.h>
#include <math.h>

#define BB 256
#define LL 1024
#define TT 64

// Scaled backward vectors (L, B, T). 64 MB static device scratch.
__device__ float g_sB[(size_t)LL * BB * TT];

// ---- packed f32x2 helpers (sm_103a) ----
#define FMA_F32X2(d, a, b, c) \
    asm("fma.rn.f32x2 %0, %1, %2, %3;" : "=l"(d) : "l"(a), "l"(b), "l"(c))
#define ADD_F32X2(d, a, b) \
    asm("add.rn.f32x2 %0, %1, %2;" : "=l"(d) : "l"(a), "l"(b))

// Compiler-only ordering fence for the warp-internal STS->LDS exchange.
// The hot loop is branchless so the warp is converged; same-warp shared
// accesses are ordered by the in-order LSU. (Single-variable experiment vs
// R13: ONLY this replaces __syncwarp; stores stay plain, unlike R11.)
#define WARP_EXCH() asm volatile("" ::: "memory")

__device__ __forceinline__ unsigned long long pack2(float lo, float hi) {
    unsigned long long r;
    asm("mov.b64 %0, {%1, %2};" : "=l"(r)
        : "r"(__float_as_uint(lo)), "r"(__float_as_uint(hi)));
    return r;
}
__device__ __forceinline__ float unpack_sum(unsigned long long v) {
    unsigned int lo, hi;
    asm("mov.b64 {%0, %1}, %2;" : "=r"(lo), "=r"(hi) : "l"(v));
    return __uint_as_float(lo) + __uint_as_float(hi);
}

// Dual-tag matvec: qA = sum_j sh[j]*wA[j], qB = sum_j sh[j]*wB[j].
__device__ __forceinline__ void matvec2(const float* shbuf,
                                        const unsigned long long* wA,
                                        const unsigned long long* wB,
                                        float& qA, float& qB) {
    const ulonglong2* sv = (const ulonglong2*)shbuf;
    unsigned long long a0 = 0, a1 = 0, a2 = 0, a3 = 0;
    unsigned long long b0 = 0, b1 = 0, b2 = 0, b3 = 0;
#pragma unroll
    for (int t = 0; t < 16; t += 2) {
        ulonglong2 v0 = sv[t];
        ulonglong2 v1 = sv[t + 1];
        FMA_F32X2(a0, v0.x, wA[2 * t + 0], a0);
        FMA_F32X2(a1, v0.y, wA[2 * t + 1], a1);
        FMA_F32X2(a2, v1.x, wA[2 * t + 2], a2);
        FMA_F32X2(a3, v1.y, wA[2 * t + 3], a3);
        FMA_F32X2(b0, v0.x, wB[2 * t + 0], b0);
        FMA_F32X2(b1, v0.y, wB[2 * t + 1], b1);
        FMA_F32X2(b2, v1.x, wB[2 * t + 2], b2);
        FMA_F32X2(b3, v1.y, wB[2 * t + 3], b3);
    }
    ADD_F32X2(a0, a0, a2);
    ADD_F32X2(a1, a1, a3);
    ADD_F32X2(a0, a0, a1);
    ADD_F32X2(b0, b0, b2);
    ADD_F32X2(b1, b1, b3);
    ADD_F32X2(b0, b0, b1);
    qA = unpack_sum(a0);
    qB = unpack_sum(b0);
}

// Exact-sum variant, used only in the short peel sections.
__device__ __forceinline__ void matvec2r(const float* shbuf,
                                         const unsigned long long* wA,
                                         const unsigned long long* wB,
                                         float& qA, float& qB, float& r) {
    const ulonglong2* sv = (const ulonglong2*)shbuf;
    unsigned long long a0 = 0, a1 = 0, a2 = 0, a3 = 0;
    unsigned long long b0 = 0, b1 = 0, b2 = 0, b3 = 0;
    unsigned long long r0 = 0, r1 = 0;
#pragma unroll
    for (int t = 0; t < 16; t += 2) {
        ulonglong2 v0 = sv[t];
        ulonglong2 v1 = sv[t + 1];
        FMA_F32X2(a0, v0.x, wA[2 * t + 0], a0);
        FMA_F32X2(a1, v0.y, wA[2 * t + 1], a1);
        FMA_F32X2(a2, v1.x, wA[2 * t + 2], a2);
        FMA_F32X2(a3, v1.y, wA[2 * t + 3], a3);
        FMA_F32X2(b0, v0.x, wB[2 * t + 0], b0);
        FMA_F32X2(b1, v0.y, wB[2 * t + 1], b1);
        FMA_F32X2(b2, v1.x, wB[2 * t + 2], b2);
        FMA_F32X2(b3, v1.y, wB[2 * t + 3], b3);
        ADD_F32X2(r0, r0, v0.x);
        ADD_F32X2(r1, r1, v0.y);
        ADD_F32X2(r0, r0, v1.x);
        ADD_F32X2(r1, r1, v1.y);
    }
    ADD_F32X2(a0, a0, a2);
    ADD_F32X2(a1, a1, a3);
    ADD_F32X2(a0, a0, a1);
    ADD_F32X2(b0, b0, b2);
    ADD_F32X2(b1, b1, b3);
    ADD_F32X2(b0, b0, b1);
    ADD_F32X2(r0, r0, r1);
    qA = unpack_sum(a0);
    qB = unpack_sum(b0);
    r = unpack_sum(r0);
}

// ---------------------------------------------------------------------------
// Fused scan: ONE WARP PER TASK; thread lane owns tags (2*lane, 2*lane+1).
// Branchless hot loop; warp-internal exchange via compiler fence (no
// WARPSYNC). Lazy normalization (1/r applied two steps late; r = sum of the
// first 4 shared values). Any lane-uniform per-(l,b) scale cancels exactly in
// crf_combine's per-position normalization.
// ---------------------------------------------------------------------------
__global__ __launch_bounds__(128) void crf_scan(
    const float* __restrict__ em,     // (B, L, T)
    const float* __restrict__ start,  // (T)
    const float* __restrict__ endt,   // (T)
    const float* __restrict__ trans,  // (T, T)
    const int*   __restrict__ mask,   // (B, L)
    float* __restrict__ sA)           // (L, B, T) = d_out
{
    const int lane = threadIdx.x & 31;
    const int w    = threadIdx.x >> 5;
    const int task = blockIdx.x * 4 + w;
    const int tAi  = 2 * lane;
    const int tBi  = tAi + 1;
    const int OSTRIDE = BB * TT / 2;   // float2 units per l-slab

    __shared__ __align__(16) float sh[4][2][TT];   // [warp][buf][tag]

    if (task < BB) {
        // ================= FORWARD =================
        const int b = task;

        unsigned long long colA[TT / 2], colB[TT / 2];
#pragma unroll
        for (int j2 = 0; j2 < TT / 2; ++j2) {
            colA[j2] = pack2(expf(trans[(2 * j2) * TT + tAi]),
                             expf(trans[(2 * j2 + 1) * TT + tAi]));
            colB[j2] = pack2(expf(trans[(2 * j2) * TT + tBi]),
                             expf(trans[(2 * j2 + 1) * TT + tBi]));
        }

        const float2* emb = (const float2*)(em + (size_t)b * LL * TT) + lane;
        const int* mk = mask + b * LL;
        float2* outp = (float2*)(sA + (size_t)b * TT) + lane;

        float2 e00 = emb[0];
        float sa = __expf(e00.x + start[tAi]);
        float sb = __expf(e00.y + start[tBi]);
        *outp = make_float2(sa, sb);

        // ---- peel l = 1..3 (exact normalize path) ----
#pragma unroll
        for (int l = 1; l <= 3; ++l) {
            float2 v = emb[(size_t)l * (TT / 2)];
            float eA = __expf(v.x), eB = __expf(v.y);
            int m = mk[l];
            int buf = l & 1;
            ((float2*)sh[w][buf])[lane] = make_float2(sa, sb);
            WARP_EXCH();
            float qA, qB, r;
            matvec2r(sh[w][buf], colA, colB, qA, qB, r);
            float inv = __fdividef(1.f, r);
            float nsa = qA * inv * eA, nsb = qB * inv * eB;
            sa = m ? nsa : sa;
            sb = m ? nsb : sb;
            outp += OSTRIDE;
            *outp = make_float2(sa, sb);
        }

        // ---- pipeline prologue ----
        float ebA[4], ebB[4];
        float2 rb[4];
        int mcur[4], mraw[4];
#pragma unroll
        for (int u = 0; u < 4; ++u) {
            float2 v = emb[(size_t)(4 + u) * (TT / 2)];
            ebA[u] = __expf(v.x);
            ebB[u] = __expf(v.y);
            mcur[u] = mk[4 + u];
        }
#pragma unroll
        for (int u = 0; u < 4; ++u) {
            rb[u]   = emb[(size_t)(8 + u) * (TT / 2)];
            mraw[u] = mk[8 + u];
        }

        float pend = 1.f;   // lazy 1/r, applied at the NEXT normalize step

        // ---- hot loop: l0 = 4..1020, no guards ----
        for (int l0 = 4; l0 <= LL - 4; l0 += 4) {
            float2 rnext[4];
            int mnext[4];
#pragma unroll
            for (int u = 0; u < 4; ++u) {
                int ln = min(l0 + 8 + u, LL - 1);   // clamp, no branch
                rnext[u] = emb[(size_t)ln * (TT / 2)];
                mnext[u] = mk[ln];
            }
            float enA[4], enB[4];
            int mcn[4];
#pragma unroll
            for (int u = 0; u < 4; ++u) {
                enA[u] = __expf(rb[u].x);
                enB[u] = __expf(rb[u].y);
                mcn[u] = mraw[u];
            }

#pragma unroll
            for (int u = 0; u < 4; ++u) {
                const int buf = u & 1;
                ((float2*)sh[w][buf])[lane] = make_float2(sa, sb);
                WARP_EXCH();
                float qA, qB;
                matvec2(sh[w][buf], colA, colB, qA, qB);
                float nsa, nsb;
                if (u & 1) {   // normalize step: apply lazy inv, refresh it
                    float eA2 = pend * ebA[u];   // off-chain (pend, eb ready)
                    float eB2 = pend * ebB[u];
                    nsa = qA * eA2;
                    nsb = qB * eB2;
                    // scale proxy: first 4 shared values (broadcast LDS.128)
                    float4 m4 = *(const float4*)sh[w][buf];
                    float rr = (m4.x + m4.y) + (m4.z + m4.w);
                    pend = __fdividef(1.f, rr);  // consumed 2 steps later
                } else {
                    nsa = qA * ebA[u];
                    nsb = qB * ebB[u];
                }
                sa = mcur[u] ? nsa : sa;   // FSEL, no branch
                sb = mcur[u] ? nsb : sb;
                outp += OSTRIDE;
                *outp = make_float2(sa, sb);
            }
#pragma unroll
            for (int u = 0; u < 4; ++u) {
                ebA[u] = enA[u]; ebB[u] = enB[u]; mcur[u] = mcn[u];
                rb[u] = rnext[u]; mraw[u] = mnext[u];
            }
        }
    } else {
        // ================= BACKWARD =================
        const int b = task - BB;

        unsigned long long rowA[TT / 2], rowB[TT / 2];
#pragma unroll
        for (int k2 = 0; k2 < TT / 2; ++k2) {
            rowA[k2] = pack2(expf(trans[tAi * TT + 2 * k2]),
                             expf(trans[tAi * TT + 2 * k2 + 1]));
            rowB[k2] = pack2(expf(trans[tBi * TT + 2 * k2]),
                             expf(trans[tBi * TT + 2 * k2 + 1]));
        }

        const float2* emb = (const float2*)(em + (size_t)b * LL * TT) + lane;
        const int* mk = mask + b * LL;
        float2* outp = (float2*)(g_sB + (size_t)(LL - 1) * BB * TT +
                                 (size_t)b * TT) + lane;

        float sa = __expf(endt[tAi]);
        float sb = __expf(endt[tBi]);
        *outp = make_float2(sa, sb);

        // ---- peel l = 1023..1021 (exact normalize path) ----
#pragma unroll
        for (int l = LL - 1; l >= LL - 3; --l) {
            float2 v = emb[(size_t)l * (TT / 2)];
            float ta = sa * __expf(v.x);
            float tb = sb * __expf(v.y);
            int m = mk[l];
            int buf = l & 1;
            ((float2*)sh[w][buf])[lane] = make_float2(ta, tb);
            WARP_EXCH();
            float qA, qB, r;
            matvec2r(sh[w][buf], rowA, rowB, qA, qB, r);
            float inv = __fdividef(1.f, r);
            float nsa = qA * inv, nsb = qB * inv;
            sa = m ? nsa : sa;
            sb = m ? nsb : sb;
            outp -= OSTRIDE;
            *outp = make_float2(sa, sb);
        }

        // ---- pipeline prologue ----
        float ebA[4], ebB[4];
        float2 rb[4];
        int mcur[4], mraw[4];
#pragma unroll
        for (int u = 0; u < 4; ++u) {
            int ln = (LL - 4) - u;
            float2 v = emb[(size_t)ln * (TT / 2)];
            ebA[u] = __expf(v.x);
            ebB[u] = __expf(v.y);
            mcur[u] = mk[ln];
        }
#pragma unroll
        for (int u = 0; u < 4; ++u) {
            int ln = (LL - 8) - u;
            rb[u]   = emb[(size_t)ln * (TT / 2)];
            mraw[u] = mk[ln];
        }

        float pend = 1.f;   // lazy 1/r

        // ---- hot loop: l0 = 1020 down to 4, no guards ----
        for (int l0 = LL - 4; l0 >= 4; l0 -= 4) {
            float2 rnext[4];
            int mnext[4];
#pragma unroll
            for (int u = 0; u < 4; ++u) {
                int ln = max(l0 - 8 - u, 1);       // clamp, no branch
                rnext[u] = emb[(size_t)ln * (TT / 2)];
                mnext[u] = mk[ln];
            }
            float enA[4], enB[4];
            int mcn[4];
#pragma unroll
            for (int u = 0; u < 4; ++u) {
                enA[u] = __expf(rb[u].x);
                enB[u] = __expf(rb[u].y);
                mcn[u] = mraw[u];
            }

#pragma unroll
            for (int u = 0; u < 4; ++u) {
                const int buf = u & 1;
                float ta = sa * ebA[u];
                float tb = sb * ebB[u];
                ((float2*)sh[w][buf])[lane] = make_float2(ta, tb);
                WARP_EXCH();
                float qA, qB;
                matvec2(sh[w][buf], rowA, rowB, qA, qB);
                float nsa, nsb;
                if (u & 1) {   // normalize step: apply lazy inv, refresh it
                    nsa = qA * pend;
                    nsb = qB * pend;
                    float4 m4 = *(const float4*)sh[w][buf];
                    float rr = (m4.x + m4.y) + (m4.z + m4.w);
                    pend = __fdividef(1.f, rr);
                } else {
                    nsa = qA;
                    nsb = qB;
                }
                sa = mcur[u] ? nsa : sa;
                sb = mcur[u] ? nsb : sb;
                outp -= OSTRIDE;
                *outp = make_float2(sa, sb);
            }
#pragma unroll
            for (int u = 0; u < 4; ++u) {
                ebA[u] = enA[u]; ebB[u] = enB[u]; mcur[u] = mcn[u];
                rb[u] = rnext[u]; mraw[u] = mnext[u];
            }
        }
    }
}

// ---------------------------------------------------------------------------
// Combine: out[p, k] = sA[p,k]*sB[p,k] / sum_k(sA[p,k]*sB[p,k]).
// One position per 16 lanes, float4 per thread, shfl-only reduction.
// ---------------------------------------------------------------------------
__global__ __launch_bounds__(256) void crf_combine(
    float* __restrict__ outA)   // (L*B, T): in = sA, out = marginals
{
    const int lane = threadIdx.x & 31;
    const int warp = threadIdx.x >> 5;
    const int half = lane >> 4;
    const int sub  = lane & 15;
    const size_t p = (size_t)blockIdx.x * 16 + warp * 2 + half;

    const size_t f4 = p * (TT / 4) + sub;
    float4 a = ((const float4*)outA)[f4];
    float4 b = ((const float4*)g_sB)[f4];
    float4 v = make_float4(a.x * b.x, a.y * b.y, a.z * b.z, a.w * b.w);
    float s = (v.x + v.y) + (v.z + v.w);
    s += __shfl_xor_sync(0xffffffffu, s, 8);
    s += __shfl_xor_sync(0xffffffffu, s, 4);
    s += __shfl_xor_sync(0xffffffffu, s, 2);
    s += __shfl_xor_sync(0xffffffffu, s, 1);
    float inv = 1.f / s;
    ((float4*)outA)[f4] =
        make_float4(v.x * inv, v.y * inv, v.z * inv, v.w * inv);
}

extern "C" void kernel_launch(void* const* d_in, const int* in_sizes, int n_in,
                              void* d_out, int out_size) {
    const float* em    = (const float*)d_in[0];  // emissions (B,L,T)
    const float* start = (const float*)d_in[1];  // start_transitions (T)
    const float* endt  = (const float*)d_in[2];  // end_transitions (T)
    const float* trans = (const float*)d_in[3];  // transitions (T,T)
    const int*   mask  = (const int*)d_in[4];    // mask (B,L)
    float* out = (float*)d_out;                  // (L,B,T)

    crf_scan<<<(2 * BB) / 4, 128>>>(em, start, endt, trans, mask, out);
    crf_combine<<<(LL * BB) / 16, 256>>>(out);
}

// round 15
// speedup vs baseline: 1.2434x; 1.2434x over previous
#include <cuda_runtime.h>
#include <math.h>

#define BB 256
#define LL 1024
#define TT 64

// Scaled backward vectors (L, B, T). 64 MB static device scratch.
__device__ float g_sB[(size_t)LL * BB * TT];

// ---- packed f32x2 helpers (sm_103a) ----
#define FMA_F32X2(d, a, b, c) \
    asm("fma.rn.f32x2 %0, %1, %2, %3;" : "=l"(d) : "l"(a), "l"(b), "l"(c))
#define ADD_F32X2(d, a, b) \
    asm("add.rn.f32x2 %0, %1, %2;" : "=l"(d) : "l"(a), "l"(b))

__device__ __forceinline__ unsigned long long pack2(float lo, float hi) {
    unsigned long long r;
    asm("mov.b64 %0, {%1, %2};" : "=l"(r)
        : "r"(__float_as_uint(lo)), "r"(__float_as_uint(hi)));
    return r;
}
__device__ __forceinline__ float unpack_sum(unsigned long long v) {
    unsigned int lo, hi;
    asm("mov.b64 {%0, %1}, %2;" : "=r"(lo), "=r"(hi) : "l"(v));
    return __uint_as_float(lo) + __uint_as_float(hi);
}

// Dual-tag matvec: qA = sum_j sh[j]*wA[j], qB = sum_j sh[j]*wB[j].
__device__ __forceinline__ void matvec2(const float* shbuf,
                                        const unsigned long long* wA,
                                        const unsigned long long* wB,
                                        float& qA, float& qB) {
    const ulonglong2* sv = (const ulonglong2*)shbuf;
    unsigned long long a0 = 0, a1 = 0, a2 = 0, a3 = 0;
    unsigned long long b0 = 0, b1 = 0, b2 = 0, b3 = 0;
#pragma unroll
    for (int t = 0; t < 16; t += 2) {
        ulonglong2 v0 = sv[t];
        ulonglong2 v1 = sv[t + 1];
        FMA_F32X2(a0, v0.x, wA[2 * t + 0], a0);
        FMA_F32X2(a1, v0.y, wA[2 * t + 1], a1);
        FMA_F32X2(a2, v1.x, wA[2 * t + 2], a2);
        FMA_F32X2(a3, v1.y, wA[2 * t + 3], a3);
        FMA_F32X2(b0, v0.x, wB[2 * t + 0], b0);
        FMA_F32X2(b1, v0.y, wB[2 * t + 1], b1);
        FMA_F32X2(b2, v1.x, wB[2 * t + 2], b2);
        FMA_F32X2(b3, v1.y, wB[2 * t + 3], b3);
    }
    ADD_F32X2(a0, a0, a2);
    ADD_F32X2(a1, a1, a3);
    ADD_F32X2(a0, a0, a1);
    ADD_F32X2(b0, b0, b2);
    ADD_F32X2(b1, b1, b3);
    ADD_F32X2(b0, b0, b1);
    qA = unpack_sum(a0);
    qB = unpack_sum(b0);
}

// Matvec variant that also exports the sum of the FIRST FOUR shared values
// (sv[0] is already in registers from iteration t=0 -- no extra LDS). Used
// as the lane-uniform scale proxy on normalize steps. Same floats, same add
// order as the former explicit float4 re-load: (f0+f1)+(f2+f3).
__device__ __forceinline__ void matvec2p(const float* shbuf,
                                         const unsigned long long* wA,
                                         const unsigned long long* wB,
                                         float& qA, float& qB, float& rr) {
    const ulonglong2* sv = (const ulonglong2*)shbuf;
    unsigned long long a0 = 0, a1 = 0, a2 = 0, a3 = 0;
    unsigned long long b0 = 0, b1 = 0, b2 = 0, b3 = 0;
    float rfirst = 0.f;
#pragma unroll
    for (int t = 0; t < 16; t += 2) {
        ulonglong2 v0 = sv[t];
        ulonglong2 v1 = sv[t + 1];
        if (t == 0) rfirst = unpack_sum(v0.x) + unpack_sum(v0.y);
        FMA_F32X2(a0, v0.x, wA[2 * t + 0], a0);
        FMA_F32X2(a1, v0.y, wA[2 * t + 1], a1);
        FMA_F32X2(a2, v1.x, wA[2 * t + 2], a2);
        FMA_F32X2(a3, v1.y, wA[2 * t + 3], a3);
        FMA_F32X2(b0, v0.x, wB[2 * t + 0], b0);
        FMA_F32X2(b1, v0.y, wB[2 * t + 1], b1);
        FMA_F32X2(b2, v1.x, wB[2 * t + 2], b2);
        FMA_F32X2(b3, v1.y, wB[2 * t + 3], b3);
    }
    ADD_F32X2(a0, a0, a2);
    ADD_F32X2(a1, a1, a3);
    ADD_F32X2(a0, a0, a1);
    ADD_F32X2(b0, b0, b2);
    ADD_F32X2(b1, b1, b3);
    ADD_F32X2(b0, b0, b1);
    qA = unpack_sum(a0);
    qB = unpack_sum(b0);
    rr = rfirst;
}

// Exact-sum variant, used only in the short peel sections.
__device__ __forceinline__ void matvec2r(const float* shbuf,
                                         const unsigned long long* wA,
                                         const unsigned long long* wB,
                                         float& qA, float& qB, float& r) {
    const ulonglong2* sv = (const ulonglong2*)shbuf;
    unsigned long long a0 = 0, a1 = 0, a2 = 0, a3 = 0;
    unsigned long long b0 = 0, b1 = 0, b2 = 0, b3 = 0;
    unsigned long long r0 = 0, r1 = 0;
#pragma unroll
    for (int t = 0; t < 16; t += 2) {
        ulonglong2 v0 = sv[t];
        ulonglong2 v1 = sv[t + 1];
        FMA_F32X2(a0, v0.x, wA[2 * t + 0], a0);
        FMA_F32X2(a1, v0.y, wA[2 * t + 1], a1);
        FMA_F32X2(a2, v1.x, wA[2 * t + 2], a2);
        FMA_F32X2(a3, v1.y, wA[2 * t + 3], a3);
        FMA_F32X2(b0, v0.x, wB[2 * t + 0], b0);
        FMA_F32X2(b1, v0.y, wB[2 * t + 1], b1);
        FMA_F32X2(b2, v1.x, wB[2 * t + 2], b2);
        FMA_F32X2(b3, v1.y, wB[2 * t + 3], b3);
        ADD_F32X2(r0, r0, v0.x);
        ADD_F32X2(r1, r1, v0.y);
        ADD_F32X2(r0, r0, v1.x);
        ADD_F32X2(r1, r1, v1.y);
    }
    ADD_F32X2(a0, a0, a2);
    ADD_F32X2(a1, a1, a3);
    ADD_F32X2(a0, a0, a1);
    ADD_F32X2(b0, b0, b2);
    ADD_F32X2(b1, b1, b3);
    ADD_F32X2(b0, b0, b1);
    ADD_F32X2(r0, r0, r1);
    qA = unpack_sum(a0);
    qB = unpack_sum(b0);
    r = unpack_sum(r0);
}

// ---------------------------------------------------------------------------
// Fused scan: ONE WARP PER TASK; thread lane owns tags (2*lane, 2*lane+1).
// Branchless hot loop; __syncwarp per step (REQUIRED: R14 showed removing it
// costs ~100cy/step -- it anchors the STS->LDS exchange scheduling).
// Lazy normalization: scale proxy = sum of first 4 shared values (taken from
// the matvec's own registers), 1/r applied two steps later. Any lane-uniform
// per-(l,b) scale cancels exactly in crf_combine.
// ---------------------------------------------------------------------------
__global__ __launch_bounds__(128) void crf_scan(
    const float* __restrict__ em,     // (B, L, T)
    const float* __restrict__ start,  // (T)
    const float* __restrict__ endt,   // (T)
    const float* __restrict__ trans,  // (T, T)
    const int*   __restrict__ mask,   // (B, L)
    float* __restrict__ sA)           // (L, B, T) = d_out
{
    const int lane = threadIdx.x & 31;
    const int w    = threadIdx.x >> 5;
    const int task = blockIdx.x * 4 + w;
    const int tAi  = 2 * lane;
    const int tBi  = tAi + 1;
    const int OSTRIDE = BB * TT / 2;   // float2 units per l-slab

    __shared__ __align__(16) float sh[4][2][TT];   // [warp][buf][tag]

    if (task < BB) {
        // ================= FORWARD =================
        const int b = task;

        unsigned long long colA[TT / 2], colB[TT / 2];
#pragma unroll
        for (int j2 = 0; j2 < TT / 2; ++j2) {
            colA[j2] = pack2(expf(trans[(2 * j2) * TT + tAi]),
                             expf(trans[(2 * j2 + 1) * TT + tAi]));
            colB[j2] = pack2(expf(trans[(2 * j2) * TT + tBi]),
                             expf(trans[(2 * j2 + 1) * TT + tBi]));
        }

        const float2* emb = (const float2*)(em + (size_t)b * LL * TT) + lane;
        const int* mk = mask + b * LL;
        float2* outp = (float2*)(sA + (size_t)b * TT) + lane;

        float2 e00 = emb[0];
        float sa = __expf(e00.x + start[tAi]);
        float sb = __expf(e00.y + start[tBi]);
        *outp = make_float2(sa, sb);

        // ---- peel l = 1..3 (exact normalize path) ----
#pragma unroll
        for (int l = 1; l <= 3; ++l) {
            float2 v = emb[(size_t)l * (TT / 2)];
            float eA = __expf(v.x), eB = __expf(v.y);
            int m = mk[l];
            int buf = l & 1;
            ((float2*)sh[w][buf])[lane] = make_float2(sa, sb);
            __syncwarp();
            float qA, qB, r;
            matvec2r(sh[w][buf], colA, colB, qA, qB, r);
            float inv = __fdividef(1.f, r);
            float nsa = qA * inv * eA, nsb = qB * inv * eB;
            sa = m ? nsa : sa;
            sb = m ? nsb : sb;
            outp += OSTRIDE;
            *outp = make_float2(sa, sb);
        }

        // ---- pipeline prologue ----
        float ebA[4], ebB[4];
        float2 rb[4];
        int mcur[4], mraw[4];
#pragma unroll
        for (int u = 0; u < 4; ++u) {
            float2 v = emb[(size_t)(4 + u) * (TT / 2)];
            ebA[u] = __expf(v.x);
            ebB[u] = __expf(v.y);
            mcur[u] = mk[4 + u];
        }
#pragma unroll
        for (int u = 0; u < 4; ++u) {
            rb[u]   = emb[(size_t)(8 + u) * (TT / 2)];
            mraw[u] = mk[8 + u];
        }

        float pend = 1.f;   // lazy 1/r, applied at the NEXT normalize step

        // ---- hot loop: l0 = 4..1020, no guards ----
        for (int l0 = 4; l0 <= LL - 4; l0 += 4) {
            float2 rnext[4];
            int mnext[4];
#pragma unroll
            for (int u = 0; u < 4; ++u) {
                int ln = min(l0 + 8 + u, LL - 1);   // clamp, no branch
                rnext[u] = emb[(size_t)ln * (TT / 2)];
                mnext[u] = mk[ln];
            }
            float enA[4], enB[4];
            int mcn[4];
#pragma unroll
            for (int u = 0; u < 4; ++u) {
                enA[u] = __expf(rb[u].x);
                enB[u] = __expf(rb[u].y);
                mcn[u] = mraw[u];
            }

#pragma unroll
            for (int u = 0; u < 4; ++u) {
                const int buf = u & 1;
                ((float2*)sh[w][buf])[lane] = make_float2(sa, sb);
                __syncwarp();
                float nsa, nsb;
                if (u & 1) {   // normalize step: apply lazy inv, refresh it
                    float qA, qB, rr;
                    matvec2p(sh[w][buf], colA, colB, qA, qB, rr);
                    float eA2 = pend * ebA[u];   // off-chain (pend, eb ready)
                    float eB2 = pend * ebB[u];
                    nsa = qA * eA2;
                    nsb = qB * eB2;
                    pend = __fdividef(1.f, rr);  // consumed 2 steps later
                } else {
                    float qA, qB;
                    matvec2(sh[w][buf], colA, colB, qA, qB);
                    nsa = qA * ebA[u];
                    nsb = qB * ebB[u];
                }
                sa = mcur[u] ? nsa : sa;   // FSEL, no branch
                sb = mcur[u] ? nsb : sb;
                outp += OSTRIDE;
                *outp = make_float2(sa, sb);
            }
#pragma unroll
            for (int u = 0; u < 4; ++u) {
                ebA[u] = enA[u]; ebB[u] = enB[u]; mcur[u] = mcn[u];
                rb[u] = rnext[u]; mraw[u] = mnext[u];
            }
        }
    } else {
        // ================= BACKWARD =================
        const int b = task - BB;

        unsigned long long rowA[TT / 2], rowB[TT / 2];
#pragma unroll
        for (int k2 = 0; k2 < TT / 2; ++k2) {
            rowA[k2] = pack2(expf(trans[tAi * TT + 2 * k2]),
                             expf(trans[tAi * TT + 2 * k2 + 1]));
            rowB[k2] = pack2(expf(trans[tBi * TT + 2 * k2]),
                             expf(trans[tBi * TT + 2 * k2 + 1]));
        }

        const float2* emb = (const float2*)(em + (size_t)b * LL * TT) + lane;
        const int* mk = mask + b * LL;
        float2* outp = (float2*)(g_sB + (size_t)(LL - 1) * BB * TT +
                                 (size_t)b * TT) + lane;

        float sa = __expf(endt[tAi]);
        float sb = __expf(endt[tBi]);
        *outp = make_float2(sa, sb);

        // ---- peel l = 1023..1021 (exact normalize path) ----
#pragma unroll
        for (int l = LL - 1; l >= LL - 3; --l) {
            float2 v = emb[(size_t)l * (TT / 2)];
            float ta = sa * __expf(v.x);
            float tb = sb * __expf(v.y);
            int m = mk[l];
            int buf = l & 1;
            ((float2*)sh[w][buf])[lane] = make_float2(ta, tb);
            __syncwarp();
            float qA, qB, r;
            matvec2r(sh[w][buf], rowA, rowB, qA, qB, r);
            float inv = __fdividef(1.f, r);
            float nsa = qA * inv, nsb = qB * inv;
            sa = m ? nsa : sa;
            sb = m ? nsb : sb;
            outp -= OSTRIDE;
            *outp = make_float2(sa, sb);
        }

        // ---- pipeline prologue ----
        float ebA[4], ebB[4];
        float2 rb[4];
        int mcur[4], mraw[4];
#pragma unroll
        for (int u = 0; u < 4; ++u) {
            int ln = (LL - 4) - u;
            float2 v = emb[(size_t)ln * (TT / 2)];
            ebA[u] = __expf(v.x);
            ebB[u] = __expf(v.y);
            mcur[u] = mk[ln];
        }
#pragma unroll
        for (int u = 0; u < 4; ++u) {
            int ln = (LL - 8) - u;
            rb[u]   = emb[(size_t)ln * (TT / 2)];
            mraw[u] = mk[ln];
        }

        float pend = 1.f;   // lazy 1/r

        // ---- hot loop: l0 = 1020 down to 4, no guards ----
        for (int l0 = LL - 4; l0 >= 4; l0 -= 4) {
            float2 rnext[4];
            int mnext[4];
#pragma unroll
            for (int u = 0; u < 4; ++u) {
                int ln = max(l0 - 8 - u, 1);       // clamp, no branch
                rnext[u] = emb[(size_t)ln * (TT / 2)];
                mnext[u] = mk[ln];
            }
            float enA[4], enB[4];
            int mcn[4];
#pragma unroll
            for (int u = 0; u < 4; ++u) {
                enA[u] = __expf(rb[u].x);
                enB[u] = __expf(rb[u].y);
                mcn[u] = mraw[u];
            }

#pragma unroll
            for (int u = 0; u < 4; ++u) {
                const int buf = u & 1;
                float ta = sa * ebA[u];
                float tb = sb * ebB[u];
                ((float2*)sh[w][buf])[lane] = make_float2(ta, tb);
                __syncwarp();
                float nsa, nsb;
                if (u & 1) {   // normalize step: apply lazy inv, refresh it
                    float qA, qB, rr;
                    matvec2p(sh[w][buf], rowA, rowB, qA, qB, rr);
                    nsa = qA * pend;
                    nsb = qB * pend;
                    pend = __fdividef(1.f, rr);
                } else {
                    float qA, qB;
                    matvec2(sh[w][buf], rowA, rowB, qA, qB);
                    nsa = qA;
                    nsb = qB;
                }
                sa = mcur[u] ? nsa : sa;
                sb = mcur[u] ? nsb : sb;
                outp -= OSTRIDE;
                *outp = make_float2(sa, sb);
            }
#pragma unroll
            for (int u = 0; u < 4; ++u) {
                ebA[u] = enA[u]; ebB[u] = enB[u]; mcur[u] = mcn[u];
                rb[u] = rnext[u]; mraw[u] = mnext[u];
            }
        }
    }
}

// ---------------------------------------------------------------------------
// Combine: out[p, k] = sA[p,k]*sB[p,k] / sum_k(sA[p,k]*sB[p,k]).
// One position per 16 lanes, float4 per thread, shfl-only reduction.
// ---------------------------------------------------------------------------
__global__ __launch_bounds__(256) void crf_combine(
    float* __restrict__ outA)   // (L*B, T): in = sA, out = marginals
{
    const int lane = threadIdx.x & 31;
    const int warp = threadIdx.x >> 5;
    const int half = lane >> 4;
    const int sub  = lane & 15;
    const size_t p = (size_t)blockIdx.x * 16 + warp * 2 + half;

    const size_t f4 = p * (TT / 4) + sub;
    float4 a = ((const float4*)outA)[f4];
    float4 b = ((const float4*)g_sB)[f4];
    float4 v = make_float4(a.x * b.x, a.y * b.y, a.z * b.z, a.w * b.w);
    float s = (v.x + v.y) + (v.z + v.w);
    s += __shfl_xor_sync(0xffffffffu, s, 8);
    s += __shfl_xor_sync(0xffffffffu, s, 4);
    s += __shfl_xor_sync(0xffffffffu, s, 2);
    s += __shfl_xor_sync(0xffffffffu, s, 1);
    float inv = 1.f / s;
    ((float4*)outA)[f4] =
        make_float4(v.x * inv, v.y * inv, v.z * inv, v.w * inv);
}

extern "C" void kernel_launch(void* const* d_in, const int* in_sizes, int n_in,
                              void* d_out, int out_size) {
    const float* em    = (const float*)d_in[0];  // emissions (B,L,T)
    const float* start = (const float*)d_in[1];  // start_transitions (T)
    const float* endt  = (const float*)d_in[2];  // end_transitions (T)
    const float* trans = (const float*)d_in[3];  // transitions (T,T)
    const int*   mask  = (const int*)d_in[4];    // mask (B,L)
    float* out = (float*)d_out;                  // (L,B,T)

    crf_scan<<<(2 * BB) / 4, 128>>>(em, start, endt, trans, mask, out);
    crf_combine<<<(LL * BB) / 16, 256>>>(out);
}

// round 16
// speedup vs baseline: 1.2897x; 1.0372x over previous
#include <cuda_runtime.h>
#include <math.h>

#define BB 256
#define LL 1024
#define TT 64

// Scaled backward vectors (L, B, T). 64 MB static device scratch.
__device__ float g_sB[(size_t)LL * BB * TT];

// ---- packed f32x2 helpers (sm_103a) ----
#define FMA_F32X2(d, a, b, c) \
    asm("fma.rn.f32x2 %0, %1, %2, %3;" : "=l"(d) : "l"(a), "l"(b), "l"(c))
#define ADD_F32X2(d, a, b) \
    asm("add.rn.f32x2 %0, %1, %2;" : "=l"(d) : "l"(a), "l"(b))

__device__ __forceinline__ unsigned long long pack2(float lo, float hi) {
    unsigned long long r;
    asm("mov.b64 %0, {%1, %2};" : "=l"(r)
        : "r"(__float_as_uint(lo)), "r"(__float_as_uint(hi)));
    return r;
}
__device__ __forceinline__ float unpack_sum(unsigned long long v) {
    unsigned int lo, hi;
    asm("mov.b64 {%0, %1}, %2;" : "=r"(lo), "=r"(hi) : "l"(v));
    return __uint_as_float(lo) + __uint_as_float(hi);
}

// Dual-tag matvec: qA = sum_j sh[j]*wA[j], qB = sum_j sh[j]*wB[j].
// 2 accumulators per tag (4 total): each accumulator is revisited every
// 4 FMA2 (~12cy at rt=3) > lat 4, so no RAW stall; combine tree is only
// 2 ADD2 (vs 6 with 4-per-tag), cutting ~8 issue-cycles/step.
__device__ __forceinline__ void matvec2(const float* shbuf,
                                        const unsigned long long* wA,
                                        const unsigned long long* wB,
                                        float& qA, float& qB) {
    const ulonglong2* sv = (const ulonglong2*)shbuf;
    unsigned long long a0 = 0, a1 = 0;
    unsigned long long b0 = 0, b1 = 0;
#pragma unroll
    for (int t = 0; t < 16; t += 2) {
        ulonglong2 v0 = sv[t];
        ulonglong2 v1 = sv[t + 1];
        FMA_F32X2(a0, v0.x, wA[2 * t + 0], a0);
        FMA_F32X2(a1, v0.y, wA[2 * t + 1], a1);
        FMA_F32X2(b0, v0.x, wB[2 * t + 0], b0);
        FMA_F32X2(b1, v0.y, wB[2 * t + 1], b1);
        FMA_F32X2(a0, v1.x, wA[2 * t + 2], a0);
        FMA_F32X2(a1, v1.y, wA[2 * t + 3], a1);
        FMA_F32X2(b0, v1.x, wB[2 * t + 2], b0);
        FMA_F32X2(b1, v1.y, wB[2 * t + 3], b1);
    }
    ADD_F32X2(a0, a0, a1);
    ADD_F32X2(b0, b0, b1);
    qA = unpack_sum(a0);
    qB = unpack_sum(b0);
}

// Exact-sum variant, used only in the short peel sections (cold path).
__device__ __forceinline__ void matvec2r(const float* shbuf,
                                         const unsigned long long* wA,
                                         const unsigned long long* wB,
                                         float& qA, float& qB, float& r) {
    const ulonglong2* sv = (const ulonglong2*)shbuf;
    unsigned long long a0 = 0, a1 = 0, a2 = 0, a3 = 0;
    unsigned long long b0 = 0, b1 = 0, b2 = 0, b3 = 0;
    unsigned long long r0 = 0, r1 = 0;
#pragma unroll
    for (int t = 0; t < 16; t += 2) {
        ulonglong2 v0 = sv[t];
        ulonglong2 v1 = sv[t + 1];
        FMA_F32X2(a0, v0.x, wA[2 * t + 0], a0);
        FMA_F32X2(a1, v0.y, wA[2 * t + 1], a1);
        FMA_F32X2(a2, v1.x, wA[2 * t + 2], a2);
        FMA_F32X2(a3, v1.y, wA[2 * t + 3], a3);
        FMA_F32X2(b0, v0.x, wB[2 * t + 0], b0);
        FMA_F32X2(b1, v0.y, wB[2 * t + 1], b1);
        FMA_F32X2(b2, v1.x, wB[2 * t + 2], b2);
        FMA_F32X2(b3, v1.y, wB[2 * t + 3], b3);
        ADD_F32X2(r0, r0, v0.x);
        ADD_F32X2(r1, r1, v0.y);
        ADD_F32X2(r0, r0, v1.x);
        ADD_F32X2(r1, r1, v1.y);
    }
    ADD_F32X2(a0, a0, a2);
    ADD_F32X2(a1, a1, a3);
    ADD_F32X2(a0, a0, a1);
    ADD_F32X2(b0, b0, b2);
    ADD_F32X2(b1, b1, b3);
    ADD_F32X2(b0, b0, b1);
    ADD_F32X2(r0, r0, r1);
    qA = unpack_sum(a0);
    qB = unpack_sum(b0);
    r = unpack_sum(r0);
}

// ---------------------------------------------------------------------------
// Fused scan: ONE WARP PER TASK; thread lane owns tags (2*lane, 2*lane+1).
// Branchless hot loop; __syncwarp per step (REQUIRED: R14 showed removing it
// costs ~100cy/step -- it anchors the STS->LDS exchange scheduling).
// Lazy normalization: scale proxy = sum of first 4 shared values (one
// broadcast LDS.128), 1/r applied two steps later. Any lane-uniform per-(l,b)
// scale cancels exactly in crf_combine's per-position normalization.
// ---------------------------------------------------------------------------
__global__ __launch_bounds__(128) void crf_scan(
    const float* __restrict__ em,     // (B, L, T)
    const float* __restrict__ start,  // (T)
    const float* __restrict__ endt,   // (T)
    const float* __restrict__ trans,  // (T, T)
    const int*   __restrict__ mask,   // (B, L)
    float* __restrict__ sA)           // (L, B, T) = d_out
{
    const int lane = threadIdx.x & 31;
    const int w    = threadIdx.x >> 5;
    const int task = blockIdx.x * 4 + w;
    const int tAi  = 2 * lane;
    const int tBi  = tAi + 1;
    const int OSTRIDE = BB * TT / 2;   // float2 units per l-slab

    __shared__ __align__(16) float sh[4][2][TT];   // [warp][buf][tag]

    if (task < BB) {
        // ================= FORWARD =================
        const int b = task;

        unsigned long long colA[TT / 2], colB[TT / 2];
#pragma unroll
        for (int j2 = 0; j2 < TT / 2; ++j2) {
            colA[j2] = pack2(expf(trans[(2 * j2) * TT + tAi]),
                             expf(trans[(2 * j2 + 1) * TT + tAi]));
            colB[j2] = pack2(expf(trans[(2 * j2) * TT + tBi]),
                             expf(trans[(2 * j2 + 1) * TT + tBi]));
        }

        const float2* emb = (const float2*)(em + (size_t)b * LL * TT) + lane;
        const int* mk = mask + b * LL;
        float2* outp = (float2*)(sA + (size_t)b * TT) + lane;

        float2 e00 = emb[0];
        float sa = __expf(e00.x + start[tAi]);
        float sb = __expf(e00.y + start[tBi]);
        *outp = make_float2(sa, sb);

        // ---- peel l = 1..3 (exact normalize path) ----
#pragma unroll
        for (int l = 1; l <= 3; ++l) {
            float2 v = emb[(size_t)l * (TT / 2)];
            float eA = __expf(v.x), eB = __expf(v.y);
            int m = mk[l];
            int buf = l & 1;
            ((float2*)sh[w][buf])[lane] = make_float2(sa, sb);
            __syncwarp();
            float qA, qB, r;
            matvec2r(sh[w][buf], colA, colB, qA, qB, r);
            float inv = __fdividef(1.f, r);
            float nsa = qA * inv * eA, nsb = qB * inv * eB;
            sa = m ? nsa : sa;
            sb = m ? nsb : sb;
            outp += OSTRIDE;
            *outp = make_float2(sa, sb);
        }

        // ---- pipeline prologue ----
        float ebA[4], ebB[4];
        float2 rb[4];
        int mcur[4], mraw[4];
#pragma unroll
        for (int u = 0; u < 4; ++u) {
            float2 v = emb[(size_t)(4 + u) * (TT / 2)];
            ebA[u] = __expf(v.x);
            ebB[u] = __expf(v.y);
            mcur[u] = mk[4 + u];
        }
#pragma unroll
        for (int u = 0; u < 4; ++u) {
            rb[u]   = emb[(size_t)(8 + u) * (TT / 2)];
            mraw[u] = mk[8 + u];
        }

        float pend = 1.f;   // lazy 1/r, applied at the NEXT normalize step

        // ---- hot loop: l0 = 4..1020, no guards ----
        for (int l0 = 4; l0 <= LL - 4; l0 += 4) {
            float2 rnext[4];
            int mnext[4];
#pragma unroll
            for (int u = 0; u < 4; ++u) {
                int ln = min(l0 + 8 + u, LL - 1);   // clamp, no branch
                rnext[u] = emb[(size_t)ln * (TT / 2)];
                mnext[u] = mk[ln];
            }
            float enA[4], enB[4];
            int mcn[4];
#pragma unroll
            for (int u = 0; u < 4; ++u) {
                enA[u] = __expf(rb[u].x);
                enB[u] = __expf(rb[u].y);
                mcn[u] = mraw[u];
            }

#pragma unroll
            for (int u = 0; u < 4; ++u) {
                const int buf = u & 1;
                ((float2*)sh[w][buf])[lane] = make_float2(sa, sb);
                __syncwarp();
                float qA, qB;
                matvec2(sh[w][buf], colA, colB, qA, qB);
                float nsa, nsb;
                if (u & 1) {   // normalize step: apply lazy inv, refresh it
                    float eA2 = pend * ebA[u];   // off-chain (pend, eb ready)
                    float eB2 = pend * ebB[u];
                    nsa = qA * eA2;
                    nsb = qB * eB2;
                    // scale proxy: first 4 shared values (broadcast LDS.128)
                    float4 m4 = *(const float4*)sh[w][buf];
                    float rr = (m4.x + m4.y) + (m4.z + m4.w);
                    pend = __fdividef(1.f, rr);  // consumed 2 steps later
                } else {
                    nsa = qA * ebA[u];
                    nsb = qB * ebB[u];
                }
                sa = mcur[u] ? nsa : sa;   // FSEL, no branch
                sb = mcur[u] ? nsb : sb;
                outp += OSTRIDE;
                *outp = make_float2(sa, sb);
            }
#pragma unroll
            for (int u = 0; u < 4; ++u) {
                ebA[u] = enA[u]; ebB[u] = enB[u]; mcur[u] = mcn[u];
                rb[u] = rnext[u]; mraw[u] = mnext[u];
            }
        }
    } else {
        // ================= BACKWARD =================
        const int b = task - BB;

        unsigned long long rowA[TT / 2], rowB[TT / 2];
#pragma unroll
        for (int k2 = 0; k2 < TT / 2; ++k2) {
            rowA[k2] = pack2(expf(trans[tAi * TT + 2 * k2]),
                             expf(trans[tAi * TT + 2 * k2 + 1]));
            rowB[k2] = pack2(expf(trans[tBi * TT + 2 * k2]),
                             expf(trans[tBi * TT + 2 * k2 + 1]));
        }

        const float2* emb = (const float2*)(em + (size_t)b * LL * TT) + lane;
        const int* mk = mask + b * LL;
        float2* outp = (float2*)(g_sB + (size_t)(LL - 1) * BB * TT +
                                 (size_t)b * TT) + lane;

        float sa = __expf(endt[tAi]);
        float sb = __expf(endt[tBi]);
        *outp = make_float2(sa, sb);

        // ---- peel l = 1023..1021 (exact normalize path) ----
#pragma unroll
        for (int l = LL - 1; l >= LL - 3; --l) {
            float2 v = emb[(size_t)l * (TT / 2)];
            float ta = sa * __expf(v.x);
            float tb = sb * __expf(v.y);
            int m = mk[l];
            int buf = l & 1;
            ((float2*)sh[w][buf])[lane] = make_float2(ta, tb);
            __syncwarp();
            float qA, qB, r;
            matvec2r(sh[w][buf], rowA, rowB, qA, qB, r);
            float inv = __fdividef(1.f, r);
            float nsa = qA * inv, nsb = qB * inv;
            sa = m ? nsa : sa;
            sb = m ? nsb : sb;
            outp -= OSTRIDE;
            *outp = make_float2(sa, sb);
        }

        // ---- pipeline prologue ----
        float ebA[4], ebB[4];
        float2 rb[4];
        int mcur[4], mraw[4];
#pragma unroll
        for (int u = 0; u < 4; ++u) {
            int ln = (LL - 4) - u;
            float2 v = emb[(size_t)ln * (TT / 2)];
            ebA[u] = __expf(v.x);
            ebB[u] = __expf(v.y);
            mcur[u] = mk[ln];
        }
#pragma unroll
        for (int u = 0; u < 4; ++u) {
            int ln = (LL - 8) - u;
            rb[u]   = emb[(size_t)ln * (TT / 2)];
            mraw[u] = mk[ln];
        }

        float pend = 1.f;   // lazy 1/r

        // ---- hot loop: l0 = 1020 down to 4, no guards ----
        for (int l0 = LL - 4; l0 >= 4; l0 -= 4) {
            float2 rnext[4];
            int mnext[4];
#pragma unroll
            for (int u = 0; u < 4; ++u) {
                int ln = max(l0 - 8 - u, 1);       // clamp, no branch
                rnext[u] = emb[(size_t)ln * (TT / 2)];
                mnext[u] = mk[ln];
            }
            float enA[4], enB[4];
            int mcn[4];
#pragma unroll
            for (int u = 0; u < 4; ++u) {
                enA[u] = __expf(rb[u].x);
                enB[u] = __expf(rb[u].y);
                mcn[u] = mraw[u];
            }

#pragma unroll
            for (int u = 0; u < 4; ++u) {
                const int buf = u & 1;
                float ta = sa * ebA[u];
                float tb = sb * ebB[u];
                ((float2*)sh[w][buf])[lane] = make_float2(ta, tb);
                __syncwarp();
                float qA, qB;
                matvec2(sh[w][buf], rowA, rowB, qA, qB);
                float nsa, nsb;
                if (u & 1) {   // normalize step: apply lazy inv, refresh it
                    nsa = qA * pend;
                    nsb = qB * pend;
                    float4 m4 = *(const float4*)sh[w][buf];
                    float rr = (m4.x + m4.y) + (m4.z + m4.w);
                    pend = __fdividef(1.f, rr);
                } else {
                    nsa = qA;
                    nsb = qB;
                }
                sa = mcur[u] ? nsa : sa;
                sb = mcur[u] ? nsb : sb;
                outp -= OSTRIDE;
                *outp = make_float2(sa, sb);
            }
#pragma unroll
            for (int u = 0; u < 4; ++u) {
                ebA[u] = enA[u]; ebB[u] = enB[u]; mcur[u] = mcn[u];
                rb[u] = rnext[u]; mraw[u] = mnext[u];
            }
        }
    }
}

// ---------------------------------------------------------------------------
// Combine: out[p, k] = sA[p,k]*sB[p,k] / sum_k(sA[p,k]*sB[p,k]).
// One position per 16 lanes, float4 per thread, shfl-only reduction.
// ---------------------------------------------------------------------------
__global__ __launch_bounds__(256) void crf_combine(
    float* __restrict__ outA)   // (L*B, T): in = sA, out = marginals
{
    const int lane = threadIdx.x & 31;
    const int warp = threadIdx.x >> 5;
    const int half = lane >> 4;
    const int sub  = lane & 15;
    const size_t p = (size_t)blockIdx.x * 16 + warp * 2 + half;

    const size_t f4 = p * (TT / 4) + sub;
    float4 a = ((const float4*)outA)[f4];
    float4 b = ((const float4*)g_sB)[f4];
    float4 v = make_float4(a.x * b.x, a.y * b.y, a.z * b.z, a.w * b.w);
    float s = (v.x + v.y) + (v.z + v.w);
    s += __shfl_xor_sync(0xffffffffu, s, 8);
    s += __shfl_xor_sync(0xffffffffu, s, 4);
    s += __shfl_xor_sync(0xffffffffu, s, 2);
    s += __shfl_xor_sync(0xffffffffu, s, 1);
    float inv = 1.f / s;
    ((float4*)outA)[f4] =
        make_float4(v.x * inv, v.y * inv, v.z * inv, v.w * inv);
}

extern "C" void kernel_launch(void* const* d_in, const int* in_sizes, int n_in,
                              void* d_out, int out_size) {
    const float* em    = (const float*)d_in[0];  // emissions (B,L,T)
    const float* start = (const float*)d_in[1];  // start_transitions (T)
    const float* endt  = (const float*)d_in[2];  // end_transitions (T)
    const float* trans = (const float*)d_in[3];  // transitions (T,T)
    const int*   mask  = (const int*)d_in[4];    // mask (B,L)
    float* out = (float*)d_out;                  // (L,B,T)

    crf_scan<<<(2 * BB) / 4, 128>>>(em, start, endt, trans, mask, out);
    crf_combine<<<(LL * BB) / 16, 256>>>(out);
}